// round 1
// baseline (speedup 1.0000x reference)
#include <cuda_runtime.h>
#include <math.h>

#define BB 2
#define C 19
#define H 128
#define W 128
#define HW (H*W)          // 16384
#define CF 256
#define SH 64
#define SW 64
#define SP (SH*SW)        // 4096

// Scratch (static device globals; no allocations)
__device__ float  g_prob[BB*C*HW];     // softmax probabilities [b][c][h][w]
__device__ float  g_tf[BB*SP*CF];      // transposed feats [b][s][c]
__device__ float  g_sim[BB*SP*9];      // per-source sims: 8 dirs + [4]=exp(-||f||^2)
__device__ double g_partial[3*128];    // per-block partials: pos[128], neg[128], cnt[128]

// ---------------- K1: softmax over 19 channels ----------------
__global__ void k_softmax(const float* __restrict__ logits) {
    int idx = blockIdx.x * blockDim.x + threadIdx.x;   // over B*H*W
    if (idx >= BB*HW) return;
    int b = idx >> 14;
    int p = idx & (HW - 1);
    const float* x = logits + (size_t)b * C * HW + p;
    float v[C];
    float m = -1e30f;
    #pragma unroll
    for (int c = 0; c < C; c++) { v[c] = x[(size_t)c * HW]; m = fmaxf(m, v[c]); }
    float s = 0.f;
    #pragma unroll
    for (int c = 0; c < C; c++) { v[c] = expf(v[c] - m); s += v[c]; }
    float inv = 1.f / s;
    float* o = g_prob + (size_t)b * C * HW + p;
    #pragma unroll
    for (int c = 0; c < C; c++) o[(size_t)c * HW] = v[c] * inv;
}

// ---------------- K2: transpose feats [b][c][p] -> [b][p][c] ----------------
__global__ void k_transpose(const float* __restrict__ feats) {
    __shared__ float tile[32][33];
    int b  = blockIdx.z;
    int p0 = blockIdx.x * 32;
    int c0 = blockIdx.y * 32;
    int tx = threadIdx.x, ty = threadIdx.y;
    tile[ty][tx] = feats[(size_t)b * CF * SP + (size_t)(c0 + ty) * SP + (p0 + tx)];
    __syncthreads();
    g_tf[(size_t)b * SP * CF + (size_t)(p0 + ty) * CF + (c0 + tx)] = tile[tx][ty];
}

// ---------------- K3: source-pixel pairwise sims (warp per source) ----------------
__global__ void k_srcsim() {
    int gw   = (blockIdx.x * blockDim.x + threadIdx.x) >> 5;
    int lane = threadIdx.x & 31;
    if (gw >= BB * SP) return;
    int b  = gw / SP;
    int s  = gw % SP;
    int sh = s >> 6, sw = s & 63;

    const float4* base = reinterpret_cast<const float4*>(g_tf + (size_t)(b * SP + s) * CF);
    float4 a0 = base[lane];        // channels 4*lane .. 4*lane+3
    float4 a1 = base[lane + 32];   // channels 128+4*lane ..

    // self-norm (for zero-padded neighbors)
    float acc = a0.x*a0.x + a0.y*a0.y + a0.z*a0.z + a0.w*a0.w
              + a1.x*a1.x + a1.y*a1.y + a1.z*a1.z + a1.w*a1.w;
    #pragma unroll
    for (int o = 16; o > 0; o >>= 1) acc += __shfl_xor_sync(0xffffffffu, acc, o);
    float* simout = g_sim + (size_t)(b * SP + s) * 9;
    if (lane == 0) simout[4] = expf(-acc);

    #pragma unroll
    for (int d = 0; d < 9; d++) {
        if (d == 4) continue;
        int nsh = sh + d / 3 - 1;
        int nsw = sw + d % 3 - 1;
        bool inr = (nsh >= 0 && nsh < SH && nsw >= 0 && nsw < SW);
        float r = 0.f;
        if (inr) {
            const float4* nb = reinterpret_cast<const float4*>(
                g_tf + (size_t)(b * SP + nsh * SW + nsw) * CF);
            float4 b0 = nb[lane], b1 = nb[lane + 32];
            float dx;
            dx = a0.x - b0.x; r += dx*dx;
            dx = a0.y - b0.y; r += dx*dx;
            dx = a0.z - b0.z; r += dx*dx;
            dx = a0.w - b0.w; r += dx*dx;
            dx = a1.x - b1.x; r += dx*dx;
            dx = a1.y - b1.y; r += dx*dx;
            dx = a1.z - b1.z; r += dx*dx;
            dx = a1.w - b1.w; r += dx*dx;
        }
        #pragma unroll
        for (int o = 16; o > 0; o >>= 1) r += __shfl_xor_sync(0xffffffffu, r, o);
        if (lane == 0) simout[d] = inr ? expf(-r) : 0.f;
    }
}

// ---------------- K4: per-pixel main kernel ----------------
__global__ void k_main(const float* __restrict__ ori, float* __restrict__ out) {
    int idx = blockIdx.x * blockDim.x + threadIdx.x;   // 0..32767
    int b = idx >> 14;
    int p = idx & (HW - 1);
    int h = p >> 7, w = p & 127;
    int sh = h >> 1, sw = w >> 1;
    int s  = sh * SW + sw;

    const float* pbase = g_prob + (size_t)b * C * HW;
    float pc[C];
    float sump = 0.f;
    #pragma unroll
    for (int c = 0; c < C; c++) { pc[c] = pbase[c * HW + p]; sump += pc[c]; }

    const float* simrow = g_sim + (size_t)(b * SP + s) * 9;
    float sim[9], pos[9], neg[9];

    #pragma unroll
    for (int k = 0; k < 9; k++) {
        int hn = h + k / 3 - 1;
        int wn = w + k % 3 - 1;
        if (hn < 0 || hn >= H || wn < 0 || wn >= W) {
            sim[k] = simrow[4];     // dist = ||f_center||^2 against zero padding
            pos[k] = 0.f;
            neg[k] = 0.f;           // sump*0 - 0
        } else {
            int dsh = (hn >> 1) - sh, dsw = (wn >> 1) - sw;
            sim[k] = (dsh == 0 && dsw == 0) ? 1.0f
                                            : simrow[(dsh + 1) * 3 + (dsw + 1)];
            const float* pq = pbase + hn * W + wn;
            float d = 0.f, sumq = 0.f;
            #pragma unroll
            for (int c = 0; c < C; c++) {
                float q = pq[c * HW];
                d += pc[c] * q;
                sumq += q;
            }
            pos[k] = d;
            neg[k] = sump * sumq - d;
        }
    }

    // state_sim = mean over 9
    float ssum = 0.f;
    #pragma unroll
    for (int k = 0; k < 9; k++) ssum += sim[k];
    out[2 + idx] = ssum * (1.f / 9.f);

    // top-(TOP_K+1)=5 by sim descending, stable ties (lower index first)
    bool used[9];
    #pragma unroll
    for (int k = 0; k < 9; k++) used[k] = false;
    float lp = 0.f;
    #pragma unroll
    for (int t = 0; t < 5; t++) {
        int bi = 0; float bv = -1e30f;
        #pragma unroll
        for (int k = 0; k < 9; k++)
            if (!used[k] && sim[k] > bv) { bv = sim[k]; bi = k; }
        used[bi] = true;
        lp += bv * (-pos[bi]);
    }
    // bottom-TOP_K=4 by sim ascending, stable ties (lower index first)
    bool used2[9];
    #pragma unroll
    for (int k = 0; k < 9; k++) used2[k] = false;
    float ln = 0.f;
    #pragma unroll
    for (int t = 0; t < 4; t++) {
        int bi = 0; float bv = 1e30f;
        #pragma unroll
        for (int k = 0; k < 9; k++)
            if (!used2[k] && sim[k] < bv) { bv = sim[k]; bi = k; }
        used2[bi] = true;
        ln += (1.f - bv) * (-neg[bi]);
    }

    // mask = upsampled feats channel 0 > 0
    float f0  = ori[(size_t)b * CF * SP + s];
    float msk = (f0 > 0.f) ? 1.f : 0.f;
    float vp = msk * lp, vn = msk * ln, vc = msk;

    // deterministic block reduction (fixed tree order)
    __shared__ float rp[256], rn[256], rc[256];
    int tid = threadIdx.x;
    rp[tid] = vp; rn[tid] = vn; rc[tid] = vc;
    __syncthreads();
    #pragma unroll
    for (int o = 128; o > 0; o >>= 1) {
        if (tid < o) {
            rp[tid] += rp[tid + o];
            rn[tid] += rn[tid + o];
            rc[tid] += rc[tid + o];
        }
        __syncthreads();
    }
    if (tid == 0) {
        g_partial[blockIdx.x]          = (double)rp[0];
        g_partial[128 + blockIdx.x]    = (double)rn[0];
        g_partial[256 + blockIdx.x]    = (double)rc[0];
    }
}

// ---------------- K5: final deterministic reduction ----------------
__global__ void k_final(float* __restrict__ out) {
    __shared__ double sp[128], sn[128], sc[128];
    int t = threadIdx.x;
    sp[t] = g_partial[t];
    sn[t] = g_partial[128 + t];
    sc[t] = g_partial[256 + t];
    __syncthreads();
    #pragma unroll
    for (int o = 64; o > 0; o >>= 1) {
        if (t < o) { sp[t] += sp[t + o]; sn[t] += sn[t + o]; sc[t] += sc[t + o]; }
        __syncthreads();
    }
    if (t == 0) {
        double cnt = sc[0];
        out[0] = (float)(sp[0] / (cnt * 5.0));   // / (cnt*(TOP_K+1)) * W_POS
        out[1] = (float)(sn[0] / (cnt * 4.0));   // / (cnt*TOP_K)     * W_NEG
    }
}

extern "C" void kernel_launch(void* const* d_in, const int* in_sizes, int n_in,
                              void* d_out, int out_size) {
    // Identify inputs by element count (robust to ordering)
    const float* ori;
    const float* logits;
    if (in_sizes[0] == BB * CF * SP) {
        ori    = (const float*)d_in[0];
        logits = (const float*)d_in[1];
    } else {
        ori    = (const float*)d_in[1];
        logits = (const float*)d_in[0];
    }
    float* out = (float*)d_out;

    k_softmax<<<128, 256>>>(logits);
    dim3 tgrid(SP / 32, CF / 32, BB);
    k_transpose<<<tgrid, dim3(32, 32)>>>(ori);
    k_srcsim<<<(BB * SP * 32) / 256, 256>>>();
    k_main<<<128, 256>>>(ori, out);
    k_final<<<1, 128>>>(out);
}